// round 1
// baseline (speedup 1.0000x reference)
#include <cuda_runtime.h>
#include <cuda_bf16.h>
#include <cstdint>

// Problem constants (from reference):
//   second_emb  [200000, 128] f32
//   context_emb [200000, 128] f32
//   v_i         [131072] i32
//   v_j         [131072] i32
//   negsamples  [5, 131072] i32
// output: scalar f32 = -mean_b( logsig(vi.vj) + sum_k logsig(-vi.neg_k) )

#define EMBED 128
#define NUM_NEG 5
#define WARPS_PER_BLOCK 8
#define MAX_PARTIALS 65536

__device__ float g_partials[MAX_PARTIALS];

__device__ __forceinline__ float log_sigmoid(float x) {
    // logsig(x) = min(x,0) - log1p(exp(-|x|))
    float ax = fabsf(x);
    return fminf(x, 0.0f) - log1pf(expf(-ax));
}

__device__ __forceinline__ float dot4(float4 a, float4 b) {
    return fmaf(a.x, b.x, fmaf(a.y, b.y, fmaf(a.z, b.z, a.w * b.w)));
}

__global__ void __launch_bounds__(WARPS_PER_BLOCK * 32)
w2v_loss_kernel(const float* __restrict__ second_emb,
                const float* __restrict__ context_emb,
                const int* __restrict__ v_i,
                const int* __restrict__ v_j,
                const int* __restrict__ negs,
                int batch)
{
    const int tid  = blockIdx.x * blockDim.x + threadIdx.x;
    const int warp = tid >> 5;
    const int lane = threadIdx.x & 31;

    float loss = 0.0f;

    if (warp < batch) {
        // gather indices (uniform within warp; lane 0 pattern not needed since
        // the broadcast load is cheap and all lanes need them for addressing)
        const int ivi = v_i[warp];
        const int ivj = v_j[warp];
        int ineg[NUM_NEG];
        #pragma unroll
        for (int k = 0; k < NUM_NEG; k++)
            ineg[k] = negs[(size_t)k * batch + warp];

        // each lane holds float4 at offset lane*4 -> one 512B coalesced row read
        const float4* vi_row = reinterpret_cast<const float4*>(
            second_emb + (size_t)ivi * EMBED);
        float4 a = __ldg(&vi_row[lane]);

        // issue all 6 context-row loads before consuming (MLP)
        float4 r[NUM_NEG + 1];
        const float4* vj_row = reinterpret_cast<const float4*>(
            context_emb + (size_t)ivj * EMBED);
        r[0] = __ldg(&vj_row[lane]);
        #pragma unroll
        for (int k = 0; k < NUM_NEG; k++) {
            const float4* nrow = reinterpret_cast<const float4*>(
                context_emb + (size_t)ineg[k] * EMBED);
            r[k + 1] = __ldg(&nrow[lane]);
        }

        // per-lane partial dots
        float d[NUM_NEG + 1];
        #pragma unroll
        for (int j = 0; j < NUM_NEG + 1; j++)
            d[j] = dot4(a, r[j]);

        // warp butterfly reduce all 6 dots
        #pragma unroll
        for (int off = 16; off > 0; off >>= 1) {
            #pragma unroll
            for (int j = 0; j < NUM_NEG + 1; j++)
                d[j] += __shfl_xor_sync(0xFFFFFFFFu, d[j], off);
        }

        if (lane == 0) {
            float l = log_sigmoid(d[0]);
            #pragma unroll
            for (int k = 0; k < NUM_NEG; k++)
                l += log_sigmoid(-d[k + 1]);
            loss = l;
        }
    }

    // block reduction (deterministic): lane0 of each warp -> shared -> warp0
    __shared__ float warp_sums[WARPS_PER_BLOCK];
    if (lane == 0)
        warp_sums[threadIdx.x >> 5] = loss;
    __syncthreads();

    if (threadIdx.x < 32) {
        float s = (threadIdx.x < WARPS_PER_BLOCK) ? warp_sums[threadIdx.x] : 0.0f;
        #pragma unroll
        for (int off = 16; off > 0; off >>= 1)
            s += __shfl_xor_sync(0xFFFFFFFFu, s, off);
        if (threadIdx.x == 0)
            g_partials[blockIdx.x] = s;
    }
}

__global__ void __launch_bounds__(256)
reduce_kernel(float* __restrict__ out, int num_partials, float inv_batch)
{
    // single block, deterministic tree reduce
    float s = 0.0f;
    for (int i = threadIdx.x; i < num_partials; i += 256)
        s += g_partials[i];

    __shared__ float sh[8];
    // warp reduce
    #pragma unroll
    for (int off = 16; off > 0; off >>= 1)
        s += __shfl_xor_sync(0xFFFFFFFFu, s, off);
    if ((threadIdx.x & 31) == 0)
        sh[threadIdx.x >> 5] = s;
    __syncthreads();
    if (threadIdx.x < 32) {
        float t = (threadIdx.x < 8) ? sh[threadIdx.x] : 0.0f;
        #pragma unroll
        for (int off = 4; off > 0; off >>= 1)
            t += __shfl_xor_sync(0xFFFFFFFFu, t, off);
        if (threadIdx.x == 0)
            out[0] = -t * inv_batch;
    }
}

extern "C" void kernel_launch(void* const* d_in, const int* in_sizes, int n_in,
                              void* d_out, int out_size)
{
    const float* second_emb  = (const float*)d_in[0];
    const float* context_emb = (const float*)d_in[1];
    const int*   v_i         = (const int*)d_in[2];
    const int*   v_j         = (const int*)d_in[3];
    const int*   negs        = (const int*)d_in[4];

    const int batch = in_sizes[2];  // 131072
    const int threads = WARPS_PER_BLOCK * 32;
    const int blocks = (batch + WARPS_PER_BLOCK - 1) / WARPS_PER_BLOCK;

    w2v_loss_kernel<<<blocks, threads>>>(second_emb, context_emb,
                                         v_i, v_j, negs, batch);
    reduce_kernel<<<1, 256>>>((float*)d_out, blocks, 1.0f / (float)batch);
}